// round 1
// baseline (speedup 1.0000x reference)
#include <cuda_runtime.h>
#include <math.h>

#define N_ROWS 8192
#define N_COLS 512
#define GRID_A 256
#define ROWS_PER_BLOCK (N_ROWS / GRID_A)   /* 32 */
#define THREADS_A 256
#define THREADS_F 512

// Deterministic per-block partials (no atomics, no zero-pass needed).
__device__ float g_partial_col[GRID_A][N_COLS];
__device__ float g_partial_S[GRID_A];
__device__ float g_partial_max[GRID_A];

__global__ void __launch_bounds__(THREADS_A)
reduce_kernel(const float* __restrict__ x) {
    __shared__ float s_warp[8];        // per-warp row-sq partials (8 warps)
    __shared__ float s_col[N_COLS];
    __shared__ float s_red[THREADS_A];

    const int tid  = threadIdx.x;
    const int grp  = tid >> 7;         // 0 or 1: which row of the pair
    const int lane = tid & 127;        // 0..127: position within row
    const int wid  = tid >> 5;         // 0..7
    const int lid  = tid & 31;

    float4 colacc = make_float4(0.f, 0.f, 0.f, 0.f);
    float  Sacc   = 0.f;
    float  maxacc = 0.f;

    const int row_base = blockIdx.x * ROWS_PER_BLOCK;
    const int iters = ROWS_PER_BLOCK / 2;   // 2 rows per iteration

    for (int it = 0; it < iters; ++it) {
        const int row = row_base + it * 2 + grp;
        const float4 v = *(reinterpret_cast<const float4*>(
                               x + (size_t)row * N_COLS) + lane);

        colacc.x += v.x; colacc.y += v.y; colacc.z += v.z; colacc.w += v.w;

        float sq = v.x * v.x + v.y * v.y + v.z * v.z + v.w * v.w;
        Sacc += sq;

        // warp-reduce sq (row is covered by 4 warps per group)
        #pragma unroll
        for (int off = 16; off > 0; off >>= 1)
            sq += __shfl_xor_sync(0xffffffffu, sq, off);
        if (lid == 0) s_warp[wid] = sq;
        __syncthreads();
        if (tid < 2) {
            const float rs = s_warp[tid * 4 + 0] + s_warp[tid * 4 + 1]
                           + s_warp[tid * 4 + 2] + s_warp[tid * 4 + 3];
            maxacc = fmaxf(maxacc, rs);
        }
        __syncthreads();
    }

    // Combine column accumulators of the two 128-thread groups.
    if (grp == 0) {
        s_col[lane * 4 + 0] = colacc.x;
        s_col[lane * 4 + 1] = colacc.y;
        s_col[lane * 4 + 2] = colacc.z;
        s_col[lane * 4 + 3] = colacc.w;
    }
    __syncthreads();
    if (grp == 1) {
        s_col[lane * 4 + 0] += colacc.x;
        s_col[lane * 4 + 1] += colacc.y;
        s_col[lane * 4 + 2] += colacc.z;
        s_col[lane * 4 + 3] += colacc.w;
    }
    __syncthreads();

    #pragma unroll
    for (int c = tid; c < N_COLS; c += THREADS_A)
        g_partial_col[blockIdx.x][c] = s_col[c];

    // Block-reduce S.
    s_red[tid] = Sacc;
    __syncthreads();
    for (int s = THREADS_A / 2; s > 0; s >>= 1) {
        if (tid < s) s_red[tid] += s_red[tid + s];
        __syncthreads();
    }
    if (tid == 0) g_partial_S[blockIdx.x] = s_red[0];

    // Max lives only in threads 0 and 1.
    if (tid == 1) s_warp[0] = maxacc;
    __syncthreads();
    if (tid == 0) g_partial_max[blockIdx.x] = fmaxf(maxacc, s_warp[0]);
}

__global__ void __launch_bounds__(THREADS_F)
finalize_kernel(float* __restrict__ out) {
    __shared__ float s_red[THREADS_F];
    const int tid = threadIdx.x;

    // Per-column total across 256 block-partials (coalesced: fixed b, tid=c).
    float sc = 0.f;
    #pragma unroll 8
    for (int b = 0; b < GRID_A; ++b)
        sc += g_partial_col[b][tid];
    float ssq = sc * sc;

    float Sp = 0.f, Mp = 0.f;
    if (tid < GRID_A) {
        Sp = g_partial_S[tid];
        Mp = g_partial_max[tid];
    }

    // Reduce ||s||^2
    s_red[tid] = ssq;
    __syncthreads();
    for (int s = THREADS_F / 2; s > 0; s >>= 1) {
        if (tid < s) s_red[tid] += s_red[tid + s];
        __syncthreads();
    }
    const float ssq_total = s_red[0];
    __syncthreads();

    // Reduce S
    s_red[tid] = Sp;
    __syncthreads();
    for (int s = THREADS_F / 2; s > 0; s >>= 1) {
        if (tid < s) s_red[tid] += s_red[tid + s];
        __syncthreads();
    }
    const float S_total = s_red[0];
    __syncthreads();

    // Reduce max
    s_red[tid] = Mp;
    __syncthreads();
    for (int s = THREADS_F / 2; s > 0; s >>= 1) {
        if (tid < s) s_red[tid] = fmaxf(s_red[tid], s_red[tid + s]);
        __syncthreads();
    }

    if (tid == 0) {
        const double numer = (double)N_ROWS * (double)S_total - (double)ssq_total;
        const double norm  = sqrt((double)s_red[0]);
        const double count = (double)N_ROWS * (double)(N_ROWS - 1) * 0.5;
        out[0] = (float)(numer / (norm * count));
    }
}

extern "C" void kernel_launch(void* const* d_in, const int* in_sizes, int n_in,
                              void* d_out, int out_size) {
    (void)in_sizes; (void)n_in; (void)out_size;
    const float* x = (const float*)d_in[0];
    float* out = (float*)d_out;

    reduce_kernel<<<GRID_A, THREADS_A>>>(x);
    finalize_kernel<<<1, THREADS_F>>>(out);
}

// round 2
// speedup vs baseline: 1.3302x; 1.3302x over previous
#include <cuda_runtime.h>
#include <math.h>

#define N_ROWS 8192
#define N_COLS 512
#define GRID_A 128
#define THREADS_A 256
#define WARPS_A (THREADS_A / 32)                  /* 8 warps */
#define ROWS_PER_WARP (N_ROWS / (GRID_A * WARPS_A))  /* 8 */

// Deterministic per-block partials (no float atomics).
__device__ float g_partial_col[GRID_A][N_COLS];
__device__ float g_partial_S[GRID_A];
__device__ float g_partial_max[GRID_A];
__device__ unsigned int g_counter;   // zero-init; last block resets to 0

__global__ void __launch_bounds__(THREADS_A)
fused_loss_kernel(const float* __restrict__ x, float* __restrict__ out) {
    __shared__ float s_colw[WARPS_A][N_COLS];   // 16 KB
    __shared__ float s_S[WARPS_A];
    __shared__ float s_M[WARPS_A];
    __shared__ float s_red[THREADS_A];
    __shared__ unsigned int s_last;

    const int tid = threadIdx.x;
    const int wid = tid >> 5;
    const int lid = tid & 31;

    // ---- streaming pass: warp-per-row, no barriers in the loop ----
    float colacc[16];                 // [pass 0..3][j 0..3]
    #pragma unroll
    for (int i = 0; i < 16; ++i) colacc[i] = 0.f;
    float Sacc = 0.f;
    float maxacc = 0.f;

    const int row_base = (blockIdx.x * WARPS_A + wid) * ROWS_PER_WARP;

    #pragma unroll
    for (int r = 0; r < ROWS_PER_WARP; ++r) {
        const float4* rp = reinterpret_cast<const float4*>(
            x + (size_t)(row_base + r) * N_COLS);
        float4 v[4];
        #pragma unroll
        for (int p = 0; p < 4; ++p) v[p] = rp[p * 32 + lid];  // coalesced

        float sq = 0.f;
        #pragma unroll
        for (int p = 0; p < 4; ++p) {
            colacc[p * 4 + 0] += v[p].x;
            colacc[p * 4 + 1] += v[p].y;
            colacc[p * 4 + 2] += v[p].z;
            colacc[p * 4 + 3] += v[p].w;
            sq += v[p].x * v[p].x + v[p].y * v[p].y
                + v[p].z * v[p].z + v[p].w * v[p].w;
        }
        Sacc += sq;

        // per-row squared norm: warp-only reduction (all lanes get result)
        float rs = sq;
        #pragma unroll
        for (int off = 16; off > 0; off >>= 1)
            rs += __shfl_xor_sync(0xffffffffu, rs, off);
        maxacc = fmaxf(maxacc, rs);
    }

    // ---- block epilogue ----
    #pragma unroll
    for (int p = 0; p < 4; ++p) {
        #pragma unroll
        for (int j = 0; j < 4; ++j)
            s_colw[wid][p * 128 + lid * 4 + j] = colacc[p * 4 + j];
    }
    // warp-reduce Sacc; maxacc already warp-uniform
    #pragma unroll
    for (int off = 16; off > 0; off >>= 1)
        Sacc += __shfl_xor_sync(0xffffffffu, Sacc, off);
    if (lid == 0) { s_S[wid] = Sacc; s_M[wid] = maxacc; }
    __syncthreads();

    // column partials: each thread sums 2 columns across 8 warps
    #pragma unroll
    for (int k = 0; k < 2; ++k) {
        const int c = tid + k * THREADS_A;
        float v = 0.f;
        #pragma unroll
        for (int w = 0; w < WARPS_A; ++w) v += s_colw[w][c];
        g_partial_col[blockIdx.x][c] = v;
    }
    if (tid == 0) {
        float Sp = 0.f, Mp = 0.f;
        #pragma unroll
        for (int w = 0; w < WARPS_A; ++w) {
            Sp += s_S[w];
            Mp = fmaxf(Mp, s_M[w]);
        }
        g_partial_S[blockIdx.x] = Sp;
        g_partial_max[blockIdx.x] = Mp;
        __threadfence();
        const unsigned int prev = atomicAdd(&g_counter, 1u);
        s_last = (prev == (unsigned int)(GRID_A - 1)) ? 1u : 0u;
    }
    __syncthreads();
    if (s_last == 0u) return;

    // ---- finalize: last block, partials warm in L2 ----
    __threadfence();   // acquire side

    // column totals: thread owns cols tid and tid+256
    float sc0 = 0.f, sc1 = 0.f;
    #pragma unroll 16
    for (int b = 0; b < GRID_A; ++b) {
        sc0 += g_partial_col[b][tid];
        sc1 += g_partial_col[b][tid + THREADS_A];
    }
    float ssq = sc0 * sc0 + sc1 * sc1;

    float Sp = g_partial_S[tid >> 1];   // dummy spread; real read below
    (void)Sp;
    float Spart = (tid < GRID_A) ? g_partial_S[tid] : 0.f;
    float Mpart = (tid < GRID_A) ? g_partial_max[tid] : 0.f;

    // reduce ||s||^2
    s_red[tid] = ssq;
    __syncthreads();
    #pragma unroll
    for (int s = THREADS_A / 2; s > 0; s >>= 1) {
        if (tid < s) s_red[tid] += s_red[tid + s];
        __syncthreads();
    }
    const float ssq_total = s_red[0];
    __syncthreads();

    // reduce S
    s_red[tid] = Spart;
    __syncthreads();
    #pragma unroll
    for (int s = THREADS_A / 2; s > 0; s >>= 1) {
        if (tid < s) s_red[tid] += s_red[tid + s];
        __syncthreads();
    }
    const float S_total = s_red[0];
    __syncthreads();

    // reduce max
    s_red[tid] = Mpart;
    __syncthreads();
    #pragma unroll
    for (int s = THREADS_A / 2; s > 0; s >>= 1) {
        if (tid < s) s_red[tid] = fmaxf(s_red[tid], s_red[tid + s]);
        __syncthreads();
    }

    if (tid == 0) {
        const double numer = (double)N_ROWS * (double)S_total - (double)ssq_total;
        const double norm  = sqrt((double)s_red[0]);
        const double count = (double)N_ROWS * (double)(N_ROWS - 1) * 0.5;
        out[0] = (float)(numer / (norm * count));
        g_counter = 0u;   // reset for next graph replay
    }
}

extern "C" void kernel_launch(void* const* d_in, const int* in_sizes, int n_in,
                              void* d_out, int out_size) {
    (void)in_sizes; (void)n_in; (void)out_size;
    const float* x = (const float*)d_in[0];
    float* out = (float*)d_out;
    fused_loss_kernel<<<GRID_A, THREADS_A>>>(x, out);
}

// round 3
// speedup vs baseline: 1.5138x; 1.1380x over previous
#include <cuda_runtime.h>
#include <math.h>

#define N_ROWS 8192
#define N_COLS 512
#define GRID_A 512
#define THREADS_A 256
#define WARPS_A 8              /* 512 blocks * 8 warps * 2 rows = 8192 rows */

#define SCALE_D   4294967296.0          /* 2^32 */
#define INV_SCALE (1.0 / 4294967296.0)

// Order-invariant integer accumulators (zero-init; last block resets).
__device__ unsigned long long g_col_ll[N_COLS];
__device__ unsigned long long g_S_ll;
__device__ int g_max_int;               // bit-cast float, values >= 0
__device__ unsigned int g_counter;

__global__ void __launch_bounds__(THREADS_A)
fused_loss_kernel(const float* __restrict__ x, float* __restrict__ out) {
    __shared__ float s_colw[WARPS_A][N_COLS];   // 16 KB
    __shared__ float s_S[WARPS_A];
    __shared__ float s_M[WARPS_A];
    __shared__ double s_red[THREADS_A];
    __shared__ unsigned int s_last;

    const int tid = threadIdx.x;
    const int wid = tid >> 5;
    const int lid = tid & 31;

    // ---- streaming: each warp owns 2 rows, 8 independent float4 loads ----
    const int row0 = (blockIdx.x * WARPS_A + wid) * 2;
    const float4* r0 = reinterpret_cast<const float4*>(x + (size_t)row0 * N_COLS);
    const float4* r1 = reinterpret_cast<const float4*>(x + (size_t)(row0 + 1) * N_COLS);

    float4 a[4], b[4];
    #pragma unroll
    for (int p = 0; p < 4; ++p) a[p] = r0[p * 32 + lid];
    #pragma unroll
    for (int p = 0; p < 4; ++p) b[p] = r1[p * 32 + lid];

    float sq0 = 0.f, sq1 = 0.f;
    #pragma unroll
    for (int p = 0; p < 4; ++p) {
        // column partial (both rows share lane->column mapping)
        s_colw[wid][p * 128 + lid * 4 + 0] = a[p].x + b[p].x;
        s_colw[wid][p * 128 + lid * 4 + 1] = a[p].y + b[p].y;
        s_colw[wid][p * 128 + lid * 4 + 2] = a[p].z + b[p].z;
        s_colw[wid][p * 128 + lid * 4 + 3] = a[p].w + b[p].w;
        sq0 += a[p].x * a[p].x + a[p].y * a[p].y + a[p].z * a[p].z + a[p].w * a[p].w;
        sq1 += b[p].x * b[p].x + b[p].y * b[p].y + b[p].z * b[p].z + b[p].w * b[p].w;
    }

    // warp-reduce both row norms
    #pragma unroll
    for (int off = 16; off > 0; off >>= 1) {
        sq0 += __shfl_xor_sync(0xffffffffu, sq0, off);
        sq1 += __shfl_xor_sync(0xffffffffu, sq1, off);
    }
    if (lid == 0) {
        s_S[wid] = sq0 + sq1;
        s_M[wid] = fmaxf(sq0, sq1);
    }
    __syncthreads();

    // ---- block epilogue: combine 8 warps, push int64 atomics ----
    #pragma unroll
    for (int k = 0; k < 2; ++k) {
        const int c = tid + k * THREADS_A;
        float v = 0.f;
        #pragma unroll
        for (int w = 0; w < WARPS_A; ++w) v += s_colw[w][c];
        const long long q = __double2ll_rn((double)v * SCALE_D);
        atomicAdd(&g_col_ll[c], (unsigned long long)q);
    }
    if (tid == 0) {
        float Sp = 0.f, Mp = 0.f;
        #pragma unroll
        for (int w = 0; w < WARPS_A; ++w) {
            Sp += s_S[w];
            Mp = fmaxf(Mp, s_M[w]);
        }
        const long long qs = __double2ll_rn((double)Sp * SCALE_D);
        atomicAdd(&g_S_ll, (unsigned long long)qs);
        atomicMax(&g_max_int, __float_as_int(Mp));
        __threadfence();
        const unsigned int prev = atomicAdd(&g_counter, 1u);
        s_last = (prev == (unsigned int)(GRID_A - 1)) ? 1u : 0u;
    }
    __syncthreads();
    if (s_last == 0u) return;

    // ---- finalize: last block; accumulators are tiny ----
    __threadfence();

    const unsigned long long c0 = g_col_ll[tid];
    const unsigned long long c1 = g_col_ll[tid + THREADS_A];
    const double d0 = (double)(long long)c0 * INV_SCALE;
    const double d1 = (double)(long long)c1 * INV_SCALE;

    s_red[tid] = d0 * d0 + d1 * d1;
    __syncthreads();
    #pragma unroll
    for (int s = THREADS_A / 2; s > 0; s >>= 1) {
        if (tid < s) s_red[tid] += s_red[tid + s];
        __syncthreads();
    }

    if (tid == 0) {
        const double ssq_total = s_red[0];
        const double S_total = (double)(long long)g_S_ll * INV_SCALE;
        const double maxsq = (double)__int_as_float(g_max_int);
        const double numer = (double)N_ROWS * S_total - ssq_total;
        const double norm = sqrt(maxsq);
        const double count = (double)N_ROWS * (double)(N_ROWS - 1) * 0.5;
        out[0] = (float)(numer / (norm * count));
        // reset scalars for next graph replay
        g_S_ll = 0ull;
        g_max_int = 0;
        g_counter = 0u;
    }
    // reset column accumulators
    g_col_ll[tid] = 0ull;
    g_col_ll[tid + THREADS_A] = 0ull;
}

extern "C" void kernel_launch(void* const* d_in, const int* in_sizes, int n_in,
                              void* d_out, int out_size) {
    (void)in_sizes; (void)n_in; (void)out_size;
    const float* x = (const float*)d_in[0];
    float* out = (float*)d_out;
    fused_loss_kernel<<<GRID_A, THREADS_A>>>(x, out);
}